// round 11
// baseline (speedup 1.0000x reference)
#include <cuda_runtime.h>
#include <math.h>

typedef unsigned long long ull;

// ---------------- scratch (no allocation allowed) ----------------
__device__ float g_meT[256 * 400];   // me transposed [k][m]
__device__ float g_kT [256 * 400];   // k transposed  [dfull][m]
__device__ float g_v  [400 * 256];   // v normal      [m][dfull]
__device__ float g_div[1024];
__device__ int   g_cnt;
__device__ int   g_prep;

__device__ __forceinline__ float gelu_exact(float x) {
    return 0.5f * x * (1.0f + erff(x * 0.70710678118654752440f));
}

// ---------------- f32x2 packed helpers ----------------
__device__ __forceinline__ ull pack2(float w) {
    ull r;
    asm("mov.b64 %0, {%1, %1};" : "=l"(r) : "r"(__float_as_uint(w)));
    return r;
}
__device__ __forceinline__ void vfma(ull& d, ull a, ull b) {
    asm("fma.rn.f32x2 %0, %1, %2, %0;" : "+l"(d) : "l"(a), "l"(b));
}
__device__ __forceinline__ float lo2(ull v) { return __uint_as_float((unsigned)v); }
__device__ __forceinline__ float hi2(ull v) { return __uint_as_float((unsigned)(v >> 32)); }

// =================================================================
// column GEMM core: thread owns output column `col` of W (leading
// dim LD). NR rows (NR/2 ull accumulators), x in smem k-major [k][NR].
// Fully-unrolled chunk loop, 3-buffer rotation, distance-2 prefetch.
// =================================================================
template<int K, int NR, int LD>
__device__ __forceinline__ void gemm_colT(const float* __restrict__ W,
                                          const float* __restrict__ xs,
                                          ull* acc, int col)
{
    constexpr int NCH = K / 8;
    const float* Wt = W + col;
    float w[3][8];
#pragma unroll
    for (int u = 0; u < 8; u++) w[0][u] = Wt[u * LD];
    if (NCH > 1) {
#pragma unroll
        for (int u = 0; u < 8; u++) w[1][u] = Wt[(8 + u) * LD];
    }
#pragma unroll
    for (int n = 0; n < NCH; n++) {
        if (n + 2 < NCH) {
#pragma unroll
            for (int u = 0; u < 8; u++)
                w[(n + 2) % 3][u] = Wt[((n + 2) * 8 + u) * LD];
        }
#pragma unroll
        for (int u = 0; u < 8; u++) {
            ull wp = pack2(w[n % 3][u]);
            const ull* xp = (const ull*)&xs[(n * 8 + u) * NR];
#pragma unroll
            for (int q = 0; q < NR / 2; q += 2) {
                ulonglong2 xv = *(const ulonglong2*)(xp + q);
                vfma(acc[q],     xv.x, wp);
                vfma(acc[q + 1], xv.y, wp);
            }
        }
    }
}

// Dual-column N=400 variant (cols t and t+256), 8 rows. Caller
// guarantees t+256 < 400 (i.e. t < 144).
template<int K>
__device__ __forceinline__ void gemm_dual400(const float* __restrict__ W,
                                             const float* __restrict__ xs,
                                             ull accA[4], ull accB[4], int t)
{
    constexpr int NCH = K / 8;
    const float* Wa = W + t;
    const float* Wb = W + t + 256;
    float a[3][8], b[3][8];
#pragma unroll
    for (int u = 0; u < 8; u++) { a[0][u] = Wa[u * 400]; b[0][u] = Wb[u * 400]; }
    if (NCH > 1) {
#pragma unroll
        for (int u = 0; u < 8; u++) { a[1][u] = Wa[(8 + u) * 400]; b[1][u] = Wb[(8 + u) * 400]; }
    }
#pragma unroll
    for (int n = 0; n < NCH; n++) {
        if (n + 2 < NCH) {
#pragma unroll
            for (int u = 0; u < 8; u++) {
                a[(n + 2) % 3][u] = Wa[((n + 2) * 8 + u) * 400];
                b[(n + 2) % 3][u] = Wb[((n + 2) * 8 + u) * 400];
            }
        }
#pragma unroll
        for (int u = 0; u < 8; u++) {
            ull wa = pack2(a[n % 3][u]);
            ull wb = pack2(b[n % 3][u]);
            const ull* xp = (const ull*)&xs[(n * 8 + u) * 8];
            ulonglong2 x0 = *(const ulonglong2*)(xp);
            ulonglong2 x1 = *(const ulonglong2*)(xp + 2);
            vfma(accA[0], x0.x, wa); vfma(accA[1], x0.y, wa);
            vfma(accA[2], x1.x, wa); vfma(accA[3], x1.y, wa);
            vfma(accB[0], x0.x, wb); vfma(accB[1], x0.y, wb);
            vfma(accB[2], x1.x, wb); vfma(accB[3], x1.y, wb);
        }
    }
}

__device__ __forceinline__ void set_bias2(ull a[2], float b) {
    ull bp = pack2(b); a[0] = bp; a[1] = bp;
}
__device__ __forceinline__ void set_bias4(ull a[4], float b) {
    ull bp = pack2(b); a[0] = bp; a[1] = bp; a[2] = bp; a[3] = bp;
}
__device__ __forceinline__ void unpack4(const ull a[2], float x[4]) {
    x[0] = lo2(a[0]); x[1] = hi2(a[0]); x[2] = lo2(a[1]); x[3] = hi2(a[1]);
}
__device__ __forceinline__ void unpack8(const ull a[4], float x[8]) {
#pragma unroll
    for (int q = 0; q < 4; q++) { x[2*q] = lo2(a[q]); x[2*q+1] = hi2(a[q]); }
}

// =================================================================
// mega kernel helpers (8 rows per block, 256 threads, 128 blocks)
// =================================================================
__device__ __forceinline__ void store_x8(float* xs, int t, const float acc[8])
{
    *(float4*)&xs[t * 8]     = make_float4(acc[0], acc[1], acc[2], acc[3]);
    *(float4*)&xs[t * 8 + 4] = make_float4(acc[4], acc[5], acc[6], acc[7]);
}

__device__ __forceinline__ void bsum8(const float v[8], float* wred, float* stats, int t)
{
    int lane = t & 31, warp = t >> 5;
#pragma unroll
    for (int r = 0; r < 8; r++) {
        float x = v[r];
#pragma unroll
        for (int o = 16; o; o >>= 1) x += __shfl_xor_sync(0xffffffffu, x, o);
        if (lane == 0) wred[warp * 8 + r] = x;
    }
    __syncthreads();
    if (t < 8) {
        float s = 0.f;
#pragma unroll
        for (int w = 0; w < 8; w++) s += wred[w * 8 + t];
        stats[t] = s;
    }
    __syncthreads();
}

__device__ __forceinline__ void bmax8(const float v[8], float* wred, float* stats, int t)
{
    int lane = t & 31, warp = t >> 5;
#pragma unroll
    for (int r = 0; r < 8; r++) {
        float x = v[r];
#pragma unroll
        for (int o = 16; o; o >>= 1) x = fmaxf(x, __shfl_xor_sync(0xffffffffu, x, o));
        if (lane == 0) wred[warp * 8 + r] = x;
    }
    __syncthreads();
    if (t < 8) {
        float s = -1e30f;
#pragma unroll
        for (int w = 0; w < 8; w++) s = fmaxf(s, wred[w * 8 + t]);
        stats[t] = s;
    }
    __syncthreads();
}

__device__ __forceinline__ void ln_apply8(float acc[8],
                                          const float* __restrict__ g,
                                          const float* __restrict__ b,
                                          int t, float* wred, float* stats)
{
    int lane = t & 31, warp = t >> 5;
#pragma unroll
    for (int r = 0; r < 8; r++) {
        float s = acc[r], q = acc[r] * acc[r];
#pragma unroll
        for (int o = 16; o; o >>= 1) {
            s += __shfl_xor_sync(0xffffffffu, s, o);
            q += __shfl_xor_sync(0xffffffffu, q, o);
        }
        if (lane == 0) { wred[warp * 16 + r] = s; wred[warp * 16 + 8 + r] = q; }
    }
    __syncthreads();
    if (t < 8) {
        float s = 0.f, q = 0.f;
#pragma unroll
        for (int w = 0; w < 8; w++) { s += wred[w * 16 + t]; q += wred[w * 16 + 8 + t]; }
        float mean = s * (1.f / 256.f);
        float var  = q * (1.f / 256.f) - mean * mean;
        stats[t]     = mean;
        stats[8 + t] = rsqrtf(var + 1e-5f);
    }
    __syncthreads();
    float gg = g[t], bb = b[t];
#pragma unroll
    for (int r = 0; r < 8; r++)
        acc[r] = (acc[r] - stats[r]) * stats[8 + r] * gg + bb;
}

// smem: xsA 2048 | xsB 2048 | ctx 2048 | sc 12800 | wred 128 | stats 64
#define SM_FLOATS (2048 * 3 + 12800 + 128 + 64)

__global__ __launch_bounds__(256)
void mega_kernel(const float* __restrict__ mf, const float* __restrict__ regtab,
                 const int* __restrict__ rid,
                 const float* __restrict__ ew1, const float* __restrict__ eb1,
                 const float* __restrict__ l1g, const float* __restrict__ l1b,
                 const float* __restrict__ ew2, const float* __restrict__ eb2,
                 const float* __restrict__ l2g, const float* __restrict__ l2b,
                 const float* __restrict__ ew3, const float* __restrict__ eb3,
                 const float* __restrict__ gw1, const float* __restrict__ gb1,
                 const float* __restrict__ gw2, const float* __restrict__ gb2,
                 const float* __restrict__ gw3, const float* __restrict__ gb3,
                 const float* __restrict__ wq,  const float* __restrict__ bq,
                 const float* __restrict__ wo,  const float* __restrict__ bo,
                 const float* __restrict__ memb, const float* __restrict__ proj_w,
                 const float* __restrict__ proj_b,
                 const float* __restrict__ wk,  const float* __restrict__ bk,
                 const float* __restrict__ wv,  const float* __restrict__ bv,
                 float* __restrict__ meT, float* __restrict__ kT,
                 float* __restrict__ v,   const float* __restrict__ mp,
                 float* __restrict__ out_pred, float* __restrict__ out_w,
                 float* __restrict__ divp, float* __restrict__ out_div)
{
    extern __shared__ float sm[];
    float* xsA   = sm;
    float* xsB   = xsA + 2048;
    float* ctxs  = xsB + 2048;
    float* sc    = ctxs + 2048;
    float* wred  = sc + 12800;
    float* stats = wred + 128;
    __shared__ int lastFlag;

    const int t  = threadIdx.x;
    const int b0 = blockIdx.x * 8;
    const bool s2 = (t < 144);

    // ================= fused prep phase (<=2 units per block) ==========
    // unit u<100: K-chain (meT, kT) for members 4u; u>=100: V-chain.
    {
        int ucnt = (blockIdx.x + 128 < 200) ? 2 : 1;
#pragma unroll 1
        for (int uu = 0; uu < ucnt; uu++) {
            int u = blockIdx.x + uu * 128;
            const bool isV = (u >= 100);
            const int g0 = (isV ? u - 100 : u) * 4;

            { int r = t >> 6, k = t & 63; xsA[k * 4 + r] = memb[(g0 + r) * 64 + k]; }
            __syncthreads();

            ull acc0[2];
            set_bias2(acc0, proj_b[t]);
            gemm_colT<64, 4, 256>(proj_w, xsA, acc0, t);
            float m[4]; unpack4(acc0, m);
            *(float4*)&xsB[t * 4] = make_float4(m[0], m[1], m[2], m[3]);
            if (!isV)
                *(float4*)&meT[t * 400 + g0] = make_float4(m[0], m[1], m[2], m[3]);
            __syncthreads();

            const float* Wp = isV ? wv : wk;
            const float* Bp = isV ? bv : bk;
            set_bias2(acc0, Bp[t]);
            gemm_colT<256, 4, 256>(Wp, xsB, acc0, t);
            float o[4]; unpack4(acc0, o);
            if (!isV) {
                *(float4*)&kT[t * 400 + g0] = make_float4(o[0], o[1], o[2], o[3]);
            } else {
                v[(g0 + 0) * 256 + t] = o[0];
                v[(g0 + 1) * 256 + t] = o[1];
                v[(g0 + 2) * 256 + t] = o[2];
                v[(g0 + 3) * 256 + t] = o[3];
            }
            __syncthreads();
        }
        __threadfence();       // release prep outputs
        if (t == 0) atomicAdd(&g_prep, ucnt);
        __syncthreads();
    }
    // ====================================================================

    if (t < 160) {
#pragma unroll
        for (int r = 0; r < 8; r++) {
            float x = (t < 128) ? mf[(b0 + r) * 128 + t]
                                : regtab[rid[b0 + r] * 32 + (t - 128)];
            xsA[t * 8 + r] = x;
        }
    }
    __syncthreads();

    float acc[8]; ull a2[4];

    // ---- enc1: K=160, LN, GELU ----
    set_bias4(a2, eb1[t]);
    gemm_colT<160, 8, 256>(ew1, xsA, a2, t);
    unpack8(a2, acc);
    ln_apply8(acc, l1g, l1b, t, wred, stats);
#pragma unroll
    for (int r = 0; r < 8; r++) acc[r] = gelu_exact(acc[r]);
    store_x8(xsB, t, acc);
    __syncthreads();

    // ---- enc2 ----
    set_bias4(a2, eb2[t]);
    gemm_colT<256, 8, 256>(ew2, xsB, a2, t);
    unpack8(a2, acc);
    ln_apply8(acc, l2g, l2b, t, wred, stats);
#pragma unroll
    for (int r = 0; r < 8; r++) acc[r] = gelu_exact(acc[r]);
    store_x8(xsA, t, acc);
    __syncthreads();

    // ---- enc3 -> ctx ----
    set_bias4(a2, eb3[t]);
    gemm_colT<256, 8, 256>(ew3, xsA, a2, t);
    unpack8(a2, acc);
    store_x8(ctxs, t, acc);
    __syncthreads();

    // ---- wg1 ----
    set_bias4(a2, gb1[t]);
    gemm_colT<256, 8, 256>(gw1, ctxs, a2, t);
    unpack8(a2, acc);
#pragma unroll
    for (int r = 0; r < 8; r++) acc[r] = gelu_exact(acc[r]);
    store_x8(xsB, t, acc);
    __syncthreads();

    // ---- wg2 ----
    set_bias4(a2, gb2[t]);
    gemm_colT<256, 8, 256>(gw2, xsB, a2, t);
    unpack8(a2, acc);
#pragma unroll
    for (int r = 0; r < 8; r++) acc[r] = gelu_exact(acc[r]);
    store_x8(xsA, t, acc);
    __syncthreads();

    // ---- wg3 -> base (kept in registers) ----
    float baseA[8], baseB[8];
    {
        ull aA[4] = {0, 0, 0, 0};
        if (s2) {
            ull aB[4] = {0, 0, 0, 0};
            gemm_dual400<256>(gw3, xsA, aA, aB, t);
            unpack8(aB, baseB);
            float b2v = gb3[t + 256];
#pragma unroll
            for (int r = 0; r < 8; r++) baseB[r] += b2v;
        } else {
            gemm_colT<256, 8, 400>(gw3, xsA, aA, t);
#pragma unroll
            for (int r = 0; r < 8; r++) baseB[r] = 0.f;
        }
        unpack8(aA, baseA);
        float b1v = gb3[t];
#pragma unroll
        for (int r = 0; r < 8; r++) baseA[r] += b1v;
    }

    // ---- q = ctx@wq + bq ----
    set_bias4(a2, bq[t]);
    gemm_colT<256, 8, 256>(wq, ctxs, a2, t);
    unpack8(a2, acc);
    store_x8(xsB, t, acc);
    __syncthreads();

    // ---- wait for prep outputs (kT, v, meT) ----
    if (t == 0) {
        while (*(volatile int*)&g_prep < 200) { }
    }
    __syncthreads();
    __threadfence();   // acquire

    // ---- scores per head -> sc[h][m][r] ----
#pragma unroll
    for (int h = 0; h < 4; h++) {
        ull aA[4] = {0, 0, 0, 0};
        if (s2) {
            ull aB[4] = {0, 0, 0, 0};
            gemm_dual400<64>(kT + h * 64 * 400, xsB + h * 64 * 8, aA, aB, t);
            float sB[8]; unpack8(aB, sB);
            float* d2 = &sc[(h * 400 + t + 256) * 8];
            *(float4*)&d2[0] = make_float4(sB[0]*0.125f, sB[1]*0.125f, sB[2]*0.125f, sB[3]*0.125f);
            *(float4*)&d2[4] = make_float4(sB[4]*0.125f, sB[5]*0.125f, sB[6]*0.125f, sB[7]*0.125f);
        } else {
            gemm_colT<64, 8, 400>(kT + h * 64 * 400, xsB + h * 64 * 8, aA, t);
        }
        float sA[8]; unpack8(aA, sA);
        float* d1 = &sc[(h * 400 + t) * 8];
        *(float4*)&d1[0] = make_float4(sA[0]*0.125f, sA[1]*0.125f, sA[2]*0.125f, sA[3]*0.125f);
        *(float4*)&d1[4] = make_float4(sA[4]*0.125f, sA[5]*0.125f, sA[6]*0.125f, sA[7]*0.125f);
    }
    __syncthreads();

    // ---- softmax over m for each (h, r): 32 pairs, warp each ----
    {
        int warp = t >> 5, lane = t & 31;
        for (int p = warp; p < 32; p += 8) {
            int h = p >> 3, r = p & 7;
            float* base = sc + h * 400 * 8 + r;
            float mx = -1e30f;
            for (int m = lane; m < 400; m += 32) mx = fmaxf(mx, base[m * 8]);
#pragma unroll
            for (int o = 16; o; o >>= 1) mx = fmaxf(mx, __shfl_xor_sync(0xffffffffu, mx, o));
            float s = 0.f;
            for (int m = lane; m < 400; m += 32) {
                float e = expf(base[m * 8] - mx);
                base[m * 8] = e;
                s += e;
            }
#pragma unroll
            for (int o = 16; o; o >>= 1) s += __shfl_xor_sync(0xffffffffu, s, o);
            float inv = 1.f / s;
            for (int m = lane; m < 400; m += 32) base[m * 8] *= inv;
        }
    }
    __syncthreads();

    // ---- att[r][t] = sum_m a[h(t)][r][m] * v[m][t] ----
    { ull z[4] = {0, 0, 0, 0};
      gemm_colT<400, 8, 256>(v, sc + (t >> 6) * 400 * 8, z, t);
      unpack8(z, acc); }
    store_x8(xsA, t, acc);
    __syncthreads();

    // ---- attended = att@wo + bo ----
    set_bias4(a2, bo[t]);
    gemm_colT<256, 8, 256>(wo, xsA, a2, t);
    unpack8(a2, acc);
    store_x8(xsB, t, acc);
    __syncthreads();

    // ---- attention_weights = attended @ me^T ----
    float awA[8], awB[8];
    {
        ull aA[4] = {0, 0, 0, 0};
        if (s2) {
            ull aB[4] = {0, 0, 0, 0};
            gemm_dual400<256>(meT, xsB, aA, aB, t);
            unpack8(aB, awB);
        } else {
            gemm_colT<256, 8, 400>(meT, xsB, aA, t);
#pragma unroll
            for (int r = 0; r < 8; r++) awB[r] = 0.f;
        }
        unpack8(aA, awA);
    }

    // ---- combine: softmax -> clip -> renorm -> w, prediction, diversity ----
    float lA[8], lB[8], m8[8];
#pragma unroll
    for (int r = 0; r < 8; r++) {
        lA[r] = baseA[r] + 0.5f * awA[r];
        lB[r] = s2 ? (baseB[r] + 0.5f * awB[r]) : -1e30f;
        m8[r] = fmaxf(lA[r], lB[r]);
    }
    bmax8(m8, wred, stats, t);
    float eA[8], eB[8];
#pragma unroll
    for (int r = 0; r < 8; r++) {
        float mx = stats[r];
        eA[r] = expf(lA[r] - mx);
        eB[r] = s2 ? expf(lB[r] - mx) : 0.f;
        m8[r] = eA[r] + eB[r];
    }
    bsum8(m8, wred, stats, t);
    float wA[8], wB[8];
#pragma unroll
    for (int r = 0; r < 8; r++) {
        float inv = 1.f / stats[r];
        wA[r] = fmaxf(eA[r] * inv, 0.001f);
        wB[r] = s2 ? fmaxf(eB[r] * inv, 0.001f) : 0.f;
        m8[r] = wA[r] + wB[r];
    }
    bsum8(m8, wred, stats, t);

    float p0[8], p1[8], p2[8], sx[8], sy[8], sz[8], tt[8];
#pragma unroll
    for (int r = 0; r < 8; r++) {
        float inv2 = 1.f / stats[r];
        wA[r] *= inv2;
        out_w[(size_t)(b0 + r) * 400 + t] = wA[r];
        const float* q1 = mp + ((size_t)(b0 + r) * 400 + t) * 3;
        float x0 = q1[0], x1 = q1[1], x2 = q1[2];
        float n2 = x0 * x0 + x1 * x1 + x2 * x2;
        float invn = 1.f / fmaxf(sqrtf(n2), 1e-12f);
        p0[r] = wA[r] * x0; p1[r] = wA[r] * x1; p2[r] = wA[r] * x2;
        sx[r] = x0 * invn;  sy[r] = x1 * invn;  sz[r] = x2 * invn;
        tt[r] = n2 * invn * invn;
        if (s2) {
            wB[r] *= inv2;
            out_w[(size_t)(b0 + r) * 400 + t + 256] = wB[r];
            const float* q2 = mp + ((size_t)(b0 + r) * 400 + t + 256) * 3;
            float y0 = q2[0], y1 = q2[1], y2 = q2[2];
            float nn = y0 * y0 + y1 * y1 + y2 * y2;
            float iv = 1.f / fmaxf(sqrtf(nn), 1e-12f);
            p0[r] += wB[r] * y0; p1[r] += wB[r] * y1; p2[r] += wB[r] * y2;
            sx[r] += y0 * iv;    sy[r] += y1 * iv;    sz[r] += y2 * iv;
            tt[r] += nn * iv * iv;
        }
    }
    bsum8(p0, wred, stats, t); float P0 = stats[t & 7];
    bsum8(p1, wred, stats, t); float P1 = stats[t & 7];
    bsum8(p2, wred, stats, t); float P2 = stats[t & 7];
    bsum8(sx, wred, stats, t); float SX = stats[t & 7];
    bsum8(sy, wred, stats, t); float SY = stats[t & 7];
    bsum8(sz, wred, stats, t); float SZ = stats[t & 7];
    bsum8(tt, wred, stats, t); float TT = stats[t & 7];
    if (t < 8) {
        out_pred[(b0 + t) * 3 + 0] = P0;
        out_pred[(b0 + t) * 3 + 1] = P1;
        out_pred[(b0 + t) * 3 + 2] = P2;
        divp[b0 + t] = SX * SX + SY * SY + SZ * SZ - TT;
    }

    // ---- last-block deterministic final reduction ----
    __syncthreads();
    if (t == 0) {
        __threadfence();
        int c = atomicAdd(&g_cnt, 1);
        lastFlag = (c == (int)gridDim.x - 1);
    }
    __syncthreads();
    if (lastFlag) {
        float s = 0.f;
        for (int i = t; i < 1024; i += 256) s += divp[i];
        int lane = t & 31, warp = t >> 5;
#pragma unroll
        for (int o = 16; o; o >>= 1) s += __shfl_xor_sync(0xffffffffu, s, o);
        if (lane == 0) wred[warp] = s;
        __syncthreads();
        if (t == 0) {
            float tot = 0.f;
#pragma unroll
            for (int w = 0; w < 8; w++) tot += wred[w];
            out_div[0] = tot / (1024.0f * 400.0f * 399.0f) * 0.1f;
            g_cnt = 0;
            g_prep = 0;
        }
    }
}

// =================================================================
extern "C" void kernel_launch(void* const* d_in, const int* in_sizes, int n_in,
                              void* d_out, int out_size)
{
    const float* mf     = (const float*)d_in[0];
    const float* mp     = (const float*)d_in[1];
    const float* regtab = (const float*)d_in[2];
    const float* enc_w1 = (const float*)d_in[3];
    const float* enc_b1 = (const float*)d_in[4];
    const float* ln1g   = (const float*)d_in[5];
    const float* ln1b   = (const float*)d_in[6];
    const float* enc_w2 = (const float*)d_in[7];
    const float* enc_b2 = (const float*)d_in[8];
    const float* ln2g   = (const float*)d_in[9];
    const float* ln2b   = (const float*)d_in[10];
    const float* enc_w3 = (const float*)d_in[11];
    const float* enc_b3 = (const float*)d_in[12];
    const float* wg_w1  = (const float*)d_in[13];
    const float* wg_b1  = (const float*)d_in[14];
    const float* wg_w2  = (const float*)d_in[15];
    const float* wg_b2  = (const float*)d_in[16];
    const float* wg_w3  = (const float*)d_in[17];
    const float* wg_b3  = (const float*)d_in[18];
    const float* memb   = (const float*)d_in[19];
    const float* proj_w = (const float*)d_in[20];
    const float* proj_b = (const float*)d_in[21];
    const float* wq     = (const float*)d_in[22];
    const float* bq     = (const float*)d_in[23];
    const float* wk     = (const float*)d_in[24];
    const float* bk     = (const float*)d_in[25];
    const float* wv     = (const float*)d_in[26];
    const float* bv     = (const float*)d_in[27];
    const float* wo     = (const float*)d_in[28];
    const float* bo     = (const float*)d_in[29];
    const int*   rid    = (const int*)d_in[30];
    float* out = (float*)d_out;

    float *meT, *kT, *v, *divp;
    cudaGetSymbolAddress((void**)&meT,  g_meT);
    cudaGetSymbolAddress((void**)&kT,   g_kT);
    cudaGetSymbolAddress((void**)&v,    g_v);
    cudaGetSymbolAddress((void**)&divp, g_div);

    const int smem_bytes = SM_FLOATS * (int)sizeof(float);
    cudaFuncSetAttribute(mega_kernel, cudaFuncAttributeMaxDynamicSharedMemorySize,
                         smem_bytes);

    mega_kernel<<<128, 256, smem_bytes>>>(
        mf, regtab, rid,
        enc_w1, enc_b1, ln1g, ln1b,
        enc_w2, enc_b2, ln2g, ln2b,
        enc_w3, enc_b3,
        wg_w1, wg_b1, wg_w2, wg_b2, wg_w3, wg_b3,
        wq, bq, wo, bo,
        memb, proj_w, proj_b, wk, bk, wv, bv,
        meT, kT, v, mp,
        out, out + 3072, divp, out + 412672);
}

// round 13
// speedup vs baseline: 1.1431x; 1.1431x over previous
#include <cuda_runtime.h>
#include <math.h>

typedef unsigned long long ull;

// ---------------- scratch (no allocation allowed) ----------------
__device__ float g_meT[256 * 400];   // me transposed [k][m]
__device__ float g_kT [256 * 400];   // k transposed  [dfull][m]
__device__ float g_v  [400 * 256];   // v normal      [m][dfull]
__device__ float g_div[1024];
__device__ int   g_cnt;
__device__ int   g_prep;

__device__ __forceinline__ float gelu_exact(float x) {
    return 0.5f * x * (1.0f + erff(x * 0.70710678118654752440f));
}

// ---------------- f32x2 packed helpers ----------------
__device__ __forceinline__ ull pack2(float w) {
    ull r;
    asm("mov.b64 %0, {%1, %1};" : "=l"(r) : "r"(__float_as_uint(w)));
    return r;
}
__device__ __forceinline__ void vfma(ull& d, ull a, ull b) {
    asm("fma.rn.f32x2 %0, %1, %2, %0;" : "+l"(d) : "l"(a), "l"(b));
}
__device__ __forceinline__ float lo2(ull v) { return __uint_as_float((unsigned)v); }
__device__ __forceinline__ float hi2(ull v) { return __uint_as_float((unsigned)(v >> 32)); }

// =================================================================
// column GEMM core: thread owns output column `col` of W (leading
// dim LD). NR rows (NR/2 ull accumulators), x in smem k-major [k][NR].
// Fully-unrolled chunk loop, 3-buffer rotation, distance-2 prefetch.
// =================================================================
template<int K, int NR, int LD>
__device__ __forceinline__ void gemm_colT(const float* __restrict__ W,
                                          const float* __restrict__ xs,
                                          ull* acc, int col)
{
    constexpr int NCH = K / 8;
    const float* Wt = W + col;
    float w[3][8];
#pragma unroll
    for (int u = 0; u < 8; u++) w[0][u] = Wt[u * LD];
    if (NCH > 1) {
#pragma unroll
        for (int u = 0; u < 8; u++) w[1][u] = Wt[(8 + u) * LD];
    }
#pragma unroll
    for (int n = 0; n < NCH; n++) {
        if (n + 2 < NCH) {
#pragma unroll
            for (int u = 0; u < 8; u++)
                w[(n + 2) % 3][u] = Wt[((n + 2) * 8 + u) * LD];
        }
#pragma unroll
        for (int u = 0; u < 8; u++) {
            ull wp = pack2(w[n % 3][u]);
            const ull* xp = (const ull*)&xs[(n * 8 + u) * NR];
#pragma unroll
            for (int q = 0; q < NR / 2; q += 2) {
                ulonglong2 xv = *(const ulonglong2*)(xp + q);
                vfma(acc[q],     xv.x, wp);
                vfma(acc[q + 1], xv.y, wp);
            }
        }
    }
}

__device__ __forceinline__ void set_bias2(ull a[2], float b) {
    ull bp = pack2(b); a[0] = bp; a[1] = bp;
}
__device__ __forceinline__ void set_bias4(ull a[4], float b) {
    ull bp = pack2(b); a[0] = bp; a[1] = bp; a[2] = bp; a[3] = bp;
}
__device__ __forceinline__ void zero2(ull a[2]) { a[0] = 0; a[1] = 0; }
__device__ __forceinline__ void zero4(ull a[4]) { a[0] = 0; a[1] = 0; a[2] = 0; a[3] = 0; }
__device__ __forceinline__ void unpack4(const ull a[2], float x[4]) {
    x[0] = lo2(a[0]); x[1] = hi2(a[0]); x[2] = lo2(a[1]); x[3] = hi2(a[1]);
}
__device__ __forceinline__ void unpack8(const ull a[4], float x[8]) {
#pragma unroll
    for (int q = 0; q < 4; q++) { x[2*q] = lo2(a[q]); x[2*q+1] = hi2(a[q]); }
}

__device__ __forceinline__ void store_x8(float* xs, int col, const float acc[8])
{
    *(float4*)&xs[col * 8]     = make_float4(acc[0], acc[1], acc[2], acc[3]);
    *(float4*)&xs[col * 8 + 4] = make_float4(acc[4], acc[5], acc[6], acc[7]);
}

// K-split partial combine (8 rows). kh==1 stores its partial; kh==0 adds.
__device__ __forceinline__ void split_combine8(ull a[4], float* pacc,
                                               int col, int kh, float out[8])
{
    if (kh) {
        float tmp[8]; unpack8(a, tmp);
        *(float4*)&pacc[col * 8]     = make_float4(tmp[0], tmp[1], tmp[2], tmp[3]);
        *(float4*)&pacc[col * 8 + 4] = make_float4(tmp[4], tmp[5], tmp[6], tmp[7]);
    }
    __syncthreads();
    if (!kh) {
        unpack8(a, out);
        float4 p0 = *(const float4*)&pacc[col * 8];
        float4 p1 = *(const float4*)&pacc[col * 8 + 4];
        out[0] += p0.x; out[1] += p0.y; out[2] += p0.z; out[3] += p0.w;
        out[4] += p1.x; out[5] += p1.y; out[6] += p1.z; out[7] += p1.w;
    }
}

__device__ __forceinline__ void split_combine4(ull a[2], float* pacc,
                                               int col, int kh, float out[4])
{
    if (kh) {
        float tmp[4]; unpack4(a, tmp);
        *(float4*)&pacc[col * 4] = make_float4(tmp[0], tmp[1], tmp[2], tmp[3]);
    }
    __syncthreads();
    if (!kh) {
        unpack4(a, out);
        float4 p = *(const float4*)&pacc[col * 4];
        out[0] += p.x; out[1] += p.y; out[2] += p.z; out[3] += p.w;
    }
}

// ---------------- block reductions (16 warps, 512 threads) ----------------
__device__ __forceinline__ void bsum8(const float v[8], float* wred, float* stats, int t)
{
    int lane = t & 31, warp = t >> 5;
#pragma unroll
    for (int r = 0; r < 8; r++) {
        float x = v[r];
#pragma unroll
        for (int o = 16; o; o >>= 1) x += __shfl_xor_sync(0xffffffffu, x, o);
        if (lane == 0) wred[warp * 8 + r] = x;
    }
    __syncthreads();
    if (t < 8) {
        float s = 0.f;
#pragma unroll
        for (int w = 0; w < 16; w++) s += wred[w * 8 + t];
        stats[t] = s;
    }
    __syncthreads();
}

__device__ __forceinline__ void bmax8(const float v[8], float* wred, float* stats, int t)
{
    int lane = t & 31, warp = t >> 5;
#pragma unroll
    for (int r = 0; r < 8; r++) {
        float x = v[r];
#pragma unroll
        for (int o = 16; o; o >>= 1) x = fmaxf(x, __shfl_xor_sync(0xffffffffu, x, o));
        if (lane == 0) wred[warp * 8 + r] = x;
    }
    __syncthreads();
    if (t < 8) {
        float s = -1e30f;
#pragma unroll
        for (int w = 0; w < 16; w++) s = fmaxf(s, wred[w * 8 + t]);
        stats[t] = s;
    }
    __syncthreads();
}

// LayerNorm over 256 columns held by kh==0 threads (warps 0-7).
__device__ __forceinline__ void ln_block(float out[8],
                                         const float* __restrict__ g,
                                         const float* __restrict__ b,
                                         int col, int kh, int t,
                                         float* wred, float* stats)
{
    if (!kh) {
        int lane = t & 31, warp = t >> 5;   // warps 0..7
#pragma unroll
        for (int r = 0; r < 8; r++) {
            float s = out[r], q = out[r] * out[r];
#pragma unroll
            for (int o = 16; o; o >>= 1) {
                s += __shfl_xor_sync(0xffffffffu, s, o);
                q += __shfl_xor_sync(0xffffffffu, q, o);
            }
            if (lane == 0) { wred[warp * 16 + r] = s; wred[warp * 16 + 8 + r] = q; }
        }
    }
    __syncthreads();
    if (t < 8) {
        float s = 0.f, q = 0.f;
#pragma unroll
        for (int w = 0; w < 8; w++) { s += wred[w * 16 + t]; q += wred[w * 16 + 8 + t]; }
        float mean = s * (1.f / 256.f);
        float var  = q * (1.f / 256.f) - mean * mean;
        stats[t]     = mean;
        stats[8 + t] = rsqrtf(var + 1e-5f);
    }
    __syncthreads();
    if (!kh) {
        float gg = g[col], bb = b[col];
#pragma unroll
        for (int r = 0; r < 8; r++)
            out[r] = (out[r] - stats[r]) * stats[8 + r] * gg + bb;
    }
}

// smem: xsA 2048 | xsB 2048 | ctx 2048 | pacc 2048 | sc 12800 | wred 256 | stats 64
#define SM_FLOATS (2048 * 4 + 12800 + 256 + 64)

__global__ __launch_bounds__(512, 1)
void mega_kernel(const float* __restrict__ mf, const float* __restrict__ regtab,
                 const int* __restrict__ rid,
                 const float* __restrict__ ew1, const float* __restrict__ eb1,
                 const float* __restrict__ l1g, const float* __restrict__ l1b,
                 const float* __restrict__ ew2, const float* __restrict__ eb2,
                 const float* __restrict__ l2g, const float* __restrict__ l2b,
                 const float* __restrict__ ew3, const float* __restrict__ eb3,
                 const float* __restrict__ gw1, const float* __restrict__ gb1,
                 const float* __restrict__ gw2, const float* __restrict__ gb2,
                 const float* __restrict__ gw3, const float* __restrict__ gb3,
                 const float* __restrict__ wq,  const float* __restrict__ bq,
                 const float* __restrict__ wo,  const float* __restrict__ bo,
                 const float* __restrict__ memb, const float* __restrict__ proj_w,
                 const float* __restrict__ proj_b,
                 const float* __restrict__ wk,  const float* __restrict__ bk,
                 const float* __restrict__ wv,  const float* __restrict__ bv,
                 float* __restrict__ meT, float* __restrict__ kT,
                 float* __restrict__ v,   const float* __restrict__ mp,
                 float* __restrict__ out_pred, float* __restrict__ out_w,
                 float* __restrict__ divp, float* __restrict__ out_div)
{
    extern __shared__ float sm[];
    float* xsA   = sm;
    float* xsB   = xsA + 2048;
    float* ctxs  = xsB + 2048;
    float* pacc  = ctxs + 2048;
    float* sc    = pacc + 2048;
    float* wred  = sc + 12800;
    float* stats = wred + 256;
    __shared__ int lastFlag;

    const int t   = threadIdx.x;
    const int col = t & 255;
    const int kh  = t >> 8;
    const int b0  = blockIdx.x * 8;
    const bool act400 = (t < 400);

    // ================= fused prep phase (<=2 units per block) ==========
    {
        int ucnt = (blockIdx.x + 128 < 200) ? 2 : 1;
#pragma unroll 1
        for (int uu = 0; uu < ucnt; uu++) {
            int u = blockIdx.x + uu * 128;
            const bool isV = (u >= 100);
            const int g0 = (isV ? u - 100 : u) * 4;

            if (t < 256) { int r = t >> 6, k = t & 63; xsA[k * 4 + r] = memb[(g0 + r) * 64 + k]; }
            __syncthreads();

            // proj: K=64 split 32/32
            ull a2[2];
            if (!kh) set_bias2(a2, proj_b[col]); else zero2(a2);
            gemm_colT<32, 4, 256>(proj_w + kh * 32 * 256, xsA + kh * 32 * 4, a2, col);
            float m4[4];
            split_combine4(a2, pacc, col, kh, m4);
            if (!kh) {
                *(float4*)&xsB[col * 4] = make_float4(m4[0], m4[1], m4[2], m4[3]);
                if (!isV)
                    *(float4*)&meT[col * 400 + g0] = make_float4(m4[0], m4[1], m4[2], m4[3]);
            }
            __syncthreads();

            // wk/wv: K=256 split 128/128
            const float* Wp = isV ? wv : wk;
            const float* Bp = isV ? bv : bk;
            if (!kh) set_bias2(a2, Bp[col]); else zero2(a2);
            gemm_colT<128, 4, 256>(Wp + kh * 128 * 256, xsB + kh * 128 * 4, a2, col);
            float o4[4];
            split_combine4(a2, pacc, col, kh, o4);
            if (!kh) {
                if (!isV) {
                    *(float4*)&kT[col * 400 + g0] = make_float4(o4[0], o4[1], o4[2], o4[3]);
                } else {
                    v[(g0 + 0) * 256 + col] = o4[0];
                    v[(g0 + 1) * 256 + col] = o4[1];
                    v[(g0 + 2) * 256 + col] = o4[2];
                    v[(g0 + 3) * 256 + col] = o4[3];
                }
            }
            __syncthreads();
        }
        __threadfence();
        if (t == 0) atomicAdd(&g_prep, ucnt);
        __syncthreads();
    }
    // ====================================================================

    if (t < 160) {
#pragma unroll
        for (int r = 0; r < 8; r++) {
            float x = (t < 128) ? mf[(b0 + r) * 128 + t]
                                : regtab[rid[b0 + r] * 32 + (t - 128)];
            xsA[t * 8 + r] = x;
        }
    }
    __syncthreads();

    float out[8]; ull a4[4];

    // ---- enc1: K=160 split 80/80, LN, GELU ----
    if (!kh) set_bias4(a4, eb1[col]); else zero4(a4);
    gemm_colT<80, 8, 256>(ew1 + kh * 80 * 256, xsA + kh * 80 * 8, a4, col);
    split_combine8(a4, pacc, col, kh, out);
    ln_block(out, l1g, l1b, col, kh, t, wred, stats);
    if (!kh) {
#pragma unroll
        for (int r = 0; r < 8; r++) out[r] = gelu_exact(out[r]);
        store_x8(xsB, col, out);
    }
    __syncthreads();

    // ---- enc2: K=256 split ----
    if (!kh) set_bias4(a4, eb2[col]); else zero4(a4);
    gemm_colT<128, 8, 256>(ew2 + kh * 128 * 256, xsB + kh * 128 * 8, a4, col);
    split_combine8(a4, pacc, col, kh, out);
    ln_block(out, l2g, l2b, col, kh, t, wred, stats);
    if (!kh) {
#pragma unroll
        for (int r = 0; r < 8; r++) out[r] = gelu_exact(out[r]);
        store_x8(xsA, col, out);
    }
    __syncthreads();

    // ---- enc3 -> ctx ----
    if (!kh) set_bias4(a4, eb3[col]); else zero4(a4);
    gemm_colT<128, 8, 256>(ew3 + kh * 128 * 256, xsA + kh * 128 * 8, a4, col);
    split_combine8(a4, pacc, col, kh, out);
    if (!kh) store_x8(ctxs, col, out);
    __syncthreads();

    // ---- wg1 ----
    if (!kh) set_bias4(a4, gb1[col]); else zero4(a4);
    gemm_colT<128, 8, 256>(gw1 + kh * 128 * 256, ctxs + kh * 128 * 8, a4, col);
    split_combine8(a4, pacc, col, kh, out);
    if (!kh) {
#pragma unroll
        for (int r = 0; r < 8; r++) out[r] = gelu_exact(out[r]);
        store_x8(xsB, col, out);
    }
    __syncthreads();

    // ---- wg2 ----
    if (!kh) set_bias4(a4, gb2[col]); else zero4(a4);
    gemm_colT<128, 8, 256>(gw2 + kh * 128 * 256, xsB + kh * 128 * 8, a4, col);
    split_combine8(a4, pacc, col, kh, out);
    if (!kh) {
#pragma unroll
        for (int r = 0; r < 8; r++) out[r] = gelu_exact(out[r]);
        store_x8(xsA, col, out);
    }
    __syncthreads();

    // ---- wg3 -> base: cols 400, full K=256, thread t<400 ----
    float baseM[8];
    {
        zero4(a4);
        if (act400) {
            gemm_colT<256, 8, 400>(gw3, xsA, a4, t);
            unpack8(a4, baseM);
            float bb = gb3[t];
#pragma unroll
            for (int r = 0; r < 8; r++) baseM[r] += bb;
        } else {
#pragma unroll
            for (int r = 0; r < 8; r++) baseM[r] = 0.f;
        }
    }

    // ---- q = ctx@wq + bq (split) ----
    if (!kh) set_bias4(a4, bq[col]); else zero4(a4);
    gemm_colT<128, 8, 256>(wq + kh * 128 * 256, ctxs + kh * 128 * 8, a4, col);
    split_combine8(a4, pacc, col, kh, out);
    if (!kh) store_x8(xsB, col, out);
    __syncthreads();

    // ---- wait for prep outputs (kT, v, meT) ----
    if (t == 0) {
        while (*(volatile int*)&g_prep < 200) { }
    }
    __syncthreads();
    __threadfence();   // acquire

    // ---- scores: per head, cols 400, K=64, thread t<400 ----
#pragma unroll
    for (int h = 0; h < 4; h++) {
        if (act400) {
            zero4(a4);
            gemm_colT<64, 8, 400>(kT + h * 64 * 400, xsB + h * 64 * 8, a4, t);
            float s8[8]; unpack8(a4, s8);
            float* d1 = &sc[(h * 400 + t) * 8];
            *(float4*)&d1[0] = make_float4(s8[0]*0.125f, s8[1]*0.125f, s8[2]*0.125f, s8[3]*0.125f);
            *(float4*)&d1[4] = make_float4(s8[4]*0.125f, s8[5]*0.125f, s8[6]*0.125f, s8[7]*0.125f);
        }
    }
    __syncthreads();

    // ---- softmax over m for each (h, r): 32 pairs, 16 warps ----
    {
        int warp = t >> 5, lane = t & 31;
        for (int p = warp; p < 32; p += 16) {
            int h = p >> 3, r = p & 7;
            float* base = sc + h * 400 * 8 + r;
            float mx = -1e30f;
            for (int m = lane; m < 400; m += 32) mx = fmaxf(mx, base[m * 8]);
#pragma unroll
            for (int o = 16; o; o >>= 1) mx = fmaxf(mx, __shfl_xor_sync(0xffffffffu, mx, o));
            float s = 0.f;
            for (int m = lane; m < 400; m += 32) {
                float e = expf(base[m * 8] - mx);
                base[m * 8] = e;
                s += e;
            }
#pragma unroll
            for (int o = 16; o; o >>= 1) s += __shfl_xor_sync(0xffffffffu, s, o);
            float inv = 1.f / s;
            for (int m = lane; m < 400; m += 32) base[m * 8] *= inv;
        }
    }
    __syncthreads();

    // ---- att: cols 256, K=400 split 200/200 ----
    zero4(a4);
    gemm_colT<200, 8, 256>(v + kh * 200 * 256,
                           sc + (col >> 6) * 3200 + kh * 1600, a4, col);
    split_combine8(a4, pacc, col, kh, out);
    if (!kh) store_x8(xsA, col, out);
    __syncthreads();

    // ---- attended = att@wo + bo (split) ----
    if (!kh) set_bias4(a4, bo[col]); else zero4(a4);
    gemm_colT<128, 8, 256>(wo + kh * 128 * 256, xsA + kh * 128 * 8, a4, col);
    split_combine8(a4, pacc, col, kh, out);
    if (!kh) store_x8(xsB, col, out);
    __syncthreads();

    // ---- attention_weights: cols 400, full K=256, thread t<400 ----
    float awM[8];
    {
        zero4(a4);
        if (act400) {
            gemm_colT<256, 8, 400>(meT, xsB, a4, t);
            unpack8(a4, awM);
        } else {
#pragma unroll
            for (int r = 0; r < 8; r++) awM[r] = 0.f;
        }
    }

    // ---- combine: softmax -> clip -> renorm -> w, prediction, diversity ----
    float l8[8];
#pragma unroll
    for (int r = 0; r < 8; r++)
        l8[r] = act400 ? (baseM[r] + 0.5f * awM[r]) : -1e30f;
    bmax8(l8, wred, stats, t);
    float e8[8], m8[8];
#pragma unroll
    for (int r = 0; r < 8; r++) {
        e8[r] = act400 ? expf(l8[r] - stats[r]) : 0.f;
        m8[r] = e8[r];
    }
    bsum8(m8, wred, stats, t);
    float w8[8];
#pragma unroll
    for (int r = 0; r < 8; r++) {
        w8[r] = act400 ? fmaxf(e8[r] / stats[r], 0.001f) : 0.f;
        m8[r] = w8[r];
    }
    bsum8(m8, wred, stats, t);

    float p0[8], p1[8], p2[8], sx[8], sy[8], sz[8], tt[8];
#pragma unroll
    for (int r = 0; r < 8; r++) {
        if (act400) {
            float wv_ = w8[r] / stats[r];
            out_w[(size_t)(b0 + r) * 400 + t] = wv_;
            const float* q1 = mp + ((size_t)(b0 + r) * 400 + t) * 3;
            float x0 = q1[0], x1 = q1[1], x2 = q1[2];
            float n2 = x0 * x0 + x1 * x1 + x2 * x2;
            float invn = 1.f / fmaxf(sqrtf(n2), 1e-12f);
            p0[r] = wv_ * x0; p1[r] = wv_ * x1; p2[r] = wv_ * x2;
            sx[r] = x0 * invn; sy[r] = x1 * invn; sz[r] = x2 * invn;
            tt[r] = n2 * invn * invn;
        } else {
            p0[r] = p1[r] = p2[r] = 0.f;
            sx[r] = sy[r] = sz[r] = tt[r] = 0.f;
        }
    }
    bsum8(p0, wred, stats, t); float P0 = stats[t & 7];
    bsum8(p1, wred, stats, t); float P1 = stats[t & 7];
    bsum8(p2, wred, stats, t); float P2 = stats[t & 7];
    bsum8(sx, wred, stats, t); float SX = stats[t & 7];
    bsum8(sy, wred, stats, t); float SY = stats[t & 7];
    bsum8(sz, wred, stats, t); float SZ = stats[t & 7];
    bsum8(tt, wred, stats, t); float TT = stats[t & 7];
    if (t < 8) {
        out_pred[(b0 + t) * 3 + 0] = P0;
        out_pred[(b0 + t) * 3 + 1] = P1;
        out_pred[(b0 + t) * 3 + 2] = P2;
        divp[b0 + t] = SX * SX + SY * SY + SZ * SZ - TT;
    }

    // ---- last-block deterministic final reduction ----
    __syncthreads();
    if (t == 0) {
        __threadfence();
        int c = atomicAdd(&g_cnt, 1);
        lastFlag = (c == (int)gridDim.x - 1);
    }
    __syncthreads();
    if (lastFlag) {
        float s = 0.f;
        for (int i = t; i < 1024; i += 512) s += divp[i];
        int lane = t & 31, warp = t >> 5;
#pragma unroll
        for (int o = 16; o; o >>= 1) s += __shfl_xor_sync(0xffffffffu, s, o);
        if (lane == 0) wred[warp] = s;
        __syncthreads();
        if (t == 0) {
            float tot = 0.f;
#pragma unroll
            for (int w = 0; w < 16; w++) tot += wred[w];
            out_div[0] = tot / (1024.0f * 400.0f * 399.0f) * 0.1f;
            g_cnt = 0;
            g_prep = 0;
        }
    }
}

// =================================================================
extern "C" void kernel_launch(void* const* d_in, const int* in_sizes, int n_in,
                              void* d_out, int out_size)
{
    const float* mf     = (const float*)d_in[0];
    const float* mp     = (const float*)d_in[1];
    const float* regtab = (const float*)d_in[2];
    const float* enc_w1 = (const float*)d_in[3];
    const float* enc_b1 = (const float*)d_in[4];
    const float* ln1g   = (const float*)d_in[5];
    const float* ln1b   = (const float*)d_in[6];
    const float* enc_w2 = (const float*)d_in[7];
    const float* enc_b2 = (const float*)d_in[8];
    const float* ln2g   = (const float*)d_in[9];
    const float* ln2b   = (const float*)d_in[10];
    const float* enc_w3 = (const float*)d_in[11];
    const float* enc_b3 = (const float*)d_in[12];
    const float* wg_w1  = (const float*)d_in[13];
    const float* wg_b1  = (const float*)d_in[14];
    const float* wg_w2  = (const float*)d_in[15];
    const float* wg_b2  = (const float*)d_in[16];
    const float* wg_w3  = (const float*)d_in[17];
    const float* wg_b3  = (const float*)d_in[18];
    const float* memb   = (const float*)d_in[19];
    const float* proj_w = (const float*)d_in[20];
    const float* proj_b = (const float*)d_in[21];
    const float* wq     = (const float*)d_in[22];
    const float* bq     = (const float*)d_in[23];
    const float* wk     = (const float*)d_in[24];
    const float* bk     = (const float*)d_in[25];
    const float* wv     = (const float*)d_in[26];
    const float* bv     = (const float*)d_in[27];
    const float* wo     = (const float*)d_in[28];
    const float* bo     = (const float*)d_in[29];
    const int*   rid    = (const int*)d_in[30];
    float* out = (float*)d_out;

    float *meT, *kT, *v, *divp;
    cudaGetSymbolAddress((void**)&meT,  g_meT);
    cudaGetSymbolAddress((void**)&kT,   g_kT);
    cudaGetSymbolAddress((void**)&v,    g_v);
    cudaGetSymbolAddress((void**)&divp, g_div);

    const int smem_bytes = SM_FLOATS * (int)sizeof(float);
    cudaFuncSetAttribute(mega_kernel, cudaFuncAttributeMaxDynamicSharedMemorySize,
                         smem_bytes);

    mega_kernel<<<128, 512, smem_bytes>>>(
        mf, regtab, rid,
        enc_w1, enc_b1, ln1g, ln1b,
        enc_w2, enc_b2, ln2g, ln2b,
        enc_w3, enc_b3,
        wg_w1, wg_b1, wg_w2, wg_b2, wg_w3, wg_b3,
        wq, bq, wo, bo,
        memb, proj_w, proj_b, wk, bk, wv, bv,
        meT, kT, v, mp,
        out, out + 3072, divp, out + 412672);
}

// round 14
// speedup vs baseline: 1.1628x; 1.0172x over previous
#include <cuda_runtime.h>
#include <math.h>

typedef unsigned long long ull;

// ---------------- scratch (no allocation allowed) ----------------
__device__ float g_meT[256 * 400];   // me transposed [k][m]
__device__ float g_kT [256 * 400];   // k transposed  [dfull][m]
__device__ float g_v  [400 * 256];   // v normal      [m][dfull]
__device__ float g_div[1024];
__device__ int   g_cnt;

__device__ __forceinline__ float gelu_exact(float x) {
    return 0.5f * x * (1.0f + erff(x * 0.70710678118654752440f));
}

// ---------------- f32x2 packed helpers ----------------
__device__ __forceinline__ ull pack2(float w) {
    ull r;
    asm("mov.b64 %0, {%1, %1};" : "=l"(r) : "r"(__float_as_uint(w)));
    return r;
}
__device__ __forceinline__ void vfma(ull& d, ull a, ull b) {
    asm("fma.rn.f32x2 %0, %1, %2, %0;" : "+l"(d) : "l"(a), "l"(b));
}
__device__ __forceinline__ float lo2(ull v) { return __uint_as_float((unsigned)v); }
__device__ __forceinline__ float hi2(ull v) { return __uint_as_float((unsigned)(v >> 32)); }

// =================================================================
// column GEMM core: thread t owns output column t (ld 256).
// 4 rows (2 ull accumulators), x in smem k-major [k][4].
// Fully-unrolled chunk loop, 3-buffer rotation -> no MOVs, true
// distance-2 prefetch, immediate-offset loads.
// =================================================================
template<int K>
__device__ __forceinline__ void gemm_col(const float* __restrict__ W,
                                         const float* __restrict__ xs,
                                         ull acc[2], int t)
{
    constexpr int NCH = K / 8;
    const float* Wt = W + t;
    float w[3][8];
#pragma unroll
    for (int u = 0; u < 8; u++) w[0][u] = Wt[u * 256];
    if (NCH > 1) {
#pragma unroll
        for (int u = 0; u < 8; u++) w[1][u] = Wt[(8 + u) * 256];
    }
#pragma unroll
    for (int n = 0; n < NCH; n++) {
        if (n + 2 < NCH) {
#pragma unroll
            for (int u = 0; u < 8; u++)
                w[(n + 2) % 3][u] = Wt[((n + 2) * 8 + u) * 256];
        }
#pragma unroll
        for (int u = 0; u < 8; u++) {
            ull wp = pack2(w[n % 3][u]);
            ulonglong2 xv = *(const ulonglong2*)&xs[(n * 8 + u) * 4];
            vfma(acc[0], xv.x, wp);
            vfma(acc[1], xv.y, wp);
        }
    }
}

// Dual-column N=400 variant (ld 400): col slots t and t+256 (t<144), 4 rows.
template<int K>
__device__ __forceinline__ void gemm_col400(const float* __restrict__ W,
                                            const float* __restrict__ xs,
                                            ull accA[2], ull accB[2],
                                            int t, bool s2)
{
    constexpr int NCH = K / 8;
    const float* Wa = W + t;
    const float* Wb = W + t + 256;
    float a[3][8], b[3][8];
#pragma unroll
    for (int u = 0; u < 8; u++) {
        a[0][u] = Wa[u * 400];
        b[0][u] = s2 ? Wb[u * 400] : 0.f;
    }
    if (NCH > 1) {
#pragma unroll
        for (int u = 0; u < 8; u++) {
            a[1][u] = Wa[(8 + u) * 400];
            b[1][u] = s2 ? Wb[(8 + u) * 400] : 0.f;
        }
    }
#pragma unroll
    for (int n = 0; n < NCH; n++) {
        if (n + 2 < NCH) {
#pragma unroll
            for (int u = 0; u < 8; u++) {
                a[(n + 2) % 3][u] = Wa[((n + 2) * 8 + u) * 400];
                b[(n + 2) % 3][u] = s2 ? Wb[((n + 2) * 8 + u) * 400] : 0.f;
            }
        }
#pragma unroll
        for (int u = 0; u < 8; u++) {
            ull wa = pack2(a[n % 3][u]);
            ull wb = pack2(b[n % 3][u]);
            ulonglong2 xv = *(const ulonglong2*)&xs[(n * 8 + u) * 4];
            vfma(accA[0], xv.x, wa); vfma(accA[1], xv.y, wa);
            vfma(accB[0], xv.x, wb); vfma(accB[1], xv.y, wb);
        }
    }
}

// Single-column N=400 variant (ld 400): col t only, 4 rows.
template<int K>
__device__ __forceinline__ void gemm_one400(const float* __restrict__ W,
                                            const float* __restrict__ xs,
                                            ull acc[2], int t)
{
    constexpr int NCH = K / 8;
    const float* Wt = W + t;
    float w[3][8];
#pragma unroll
    for (int u = 0; u < 8; u++) w[0][u] = Wt[u * 400];
    if (NCH > 1) {
#pragma unroll
        for (int u = 0; u < 8; u++) w[1][u] = Wt[(8 + u) * 400];
    }
#pragma unroll
    for (int n = 0; n < NCH; n++) {
        if (n + 2 < NCH) {
#pragma unroll
            for (int u = 0; u < 8; u++)
                w[(n + 2) % 3][u] = Wt[((n + 2) * 8 + u) * 400];
        }
#pragma unroll
        for (int u = 0; u < 8; u++) {
            ull wp = pack2(w[n % 3][u]);
            ulonglong2 xv = *(const ulonglong2*)&xs[(n * 8 + u) * 4];
            vfma(acc[0], xv.x, wp);
            vfma(acc[1], xv.y, wp);
        }
    }
}

__device__ __forceinline__ void set_bias2(ull a[2], float b) {
    ull bp = pack2(b);
    a[0] = bp; a[1] = bp;
}
__device__ __forceinline__ void unpack4(const ull a[2], float x[4]) {
    x[0] = lo2(a[0]); x[1] = hi2(a[0]); x[2] = lo2(a[1]); x[3] = hi2(a[1]);
}

// =================================================================
// prep: me = memb@proj_w+b (recomputed per y-branch; row-local chain)
//       y=0: write meT, compute kT    y=1: compute v
// grid (100, 2), 4 member rows per block.
// =================================================================
__global__ __launch_bounds__(256)
void prep_kernel(const float* __restrict__ memb,
                 const float* __restrict__ proj_w, const float* __restrict__ proj_b,
                 const float* __restrict__ wk, const float* __restrict__ bk,
                 const float* __restrict__ wv, const float* __restrict__ bv,
                 float* __restrict__ meT, float* __restrict__ kT, float* __restrict__ v)
{
    __shared__ float xm[64 * 4];
    __shared__ float mes[256 * 4];
    const int t = threadIdx.x;
    const int g0 = blockIdx.x * 4;
    const bool isV = (blockIdx.y != 0);

    { int r = t >> 6, k = t & 63; xm[k * 4 + r] = memb[(g0 + r) * 64 + k]; }
    __syncthreads();

    ull acc[2];
    set_bias2(acc, proj_b[t]);
    gemm_col<64>(proj_w, xm, acc, t);
    float m[4]; unpack4(acc, m);
    *(float4*)&mes[t * 4] = make_float4(m[0], m[1], m[2], m[3]);
    if (!isV)
        *(float4*)&meT[t * 400 + g0] = make_float4(m[0], m[1], m[2], m[3]);
    __syncthreads();

    const float* W = isV ? wv : wk;
    const float* B = isV ? bv : bk;
    set_bias2(acc, B[t]);
    gemm_col<256>(W, mes, acc, t);
    float o[4]; unpack4(acc, o);
    if (!isV) {
        *(float4*)&kT[t * 400 + g0] = make_float4(o[0], o[1], o[2], o[3]);
    } else {
        v[(g0 + 0) * 256 + t] = o[0];
        v[(g0 + 1) * 256 + t] = o[1];
        v[(g0 + 2) * 256 + t] = o[2];
        v[(g0 + 3) * 256 + t] = o[3];
    }
}

// =================================================================
// mega kernel helpers (4 rows per block, 256 threads, 256 blocks)
// =================================================================
__device__ __forceinline__ void store_x(float* xs, int t, const float acc[4])
{
    *(float4*)&xs[t * 4] = make_float4(acc[0], acc[1], acc[2], acc[3]);
}

__device__ __forceinline__ void bsum4(const float v[4], float* wred, float* stats, int t)
{
    int lane = t & 31, warp = t >> 5;
#pragma unroll
    for (int r = 0; r < 4; r++) {
        float x = v[r];
#pragma unroll
        for (int o = 16; o; o >>= 1) x += __shfl_xor_sync(0xffffffffu, x, o);
        if (lane == 0) wred[warp * 4 + r] = x;
    }
    __syncthreads();
    if (t < 4) {
        float s = 0.f;
#pragma unroll
        for (int w = 0; w < 8; w++) s += wred[w * 4 + t];
        stats[t] = s;
    }
    __syncthreads();
}

__device__ __forceinline__ void bmax4(const float v[4], float* wred, float* stats, int t)
{
    int lane = t & 31, warp = t >> 5;
#pragma unroll
    for (int r = 0; r < 4; r++) {
        float x = v[r];
#pragma unroll
        for (int o = 16; o; o >>= 1) x = fmaxf(x, __shfl_xor_sync(0xffffffffu, x, o));
        if (lane == 0) wred[warp * 4 + r] = x;
    }
    __syncthreads();
    if (t < 4) {
        float s = -1e30f;
#pragma unroll
        for (int w = 0; w < 8; w++) s = fmaxf(s, wred[w * 4 + t]);
        stats[t] = s;
    }
    __syncthreads();
}

__device__ __forceinline__ void ln_apply(float acc[4],
                                         const float* __restrict__ g,
                                         const float* __restrict__ b,
                                         int t, float* wred, float* stats)
{
    int lane = t & 31, warp = t >> 5;
#pragma unroll
    for (int r = 0; r < 4; r++) {
        float s = acc[r], q = acc[r] * acc[r];
#pragma unroll
        for (int o = 16; o; o >>= 1) {
            s += __shfl_xor_sync(0xffffffffu, s, o);
            q += __shfl_xor_sync(0xffffffffu, q, o);
        }
        if (lane == 0) { wred[warp * 8 + r] = s; wred[warp * 8 + 4 + r] = q; }
    }
    __syncthreads();
    if (t < 4) {
        float s = 0.f, q = 0.f;
#pragma unroll
        for (int w = 0; w < 8; w++) { s += wred[w * 8 + t]; q += wred[w * 8 + 4 + t]; }
        float mean = s * (1.f / 256.f);
        float var  = q * (1.f / 256.f) - mean * mean;
        stats[t]     = mean;
        stats[4 + t] = rsqrtf(var + 1e-5f);
    }
    __syncthreads();
    float gg = g[t], bb = b[t];
#pragma unroll
    for (int r = 0; r < 4; r++)
        acc[r] = (acc[r] - stats[r]) * stats[4 + r] * gg + bb;
}

// smem: xsA 1024 | xsB 1024 | ctx 1024 | sc 6400 | wred 64 | stats 32
#define SM_FLOATS (1024 * 3 + 6400 + 64 + 32)

__global__ __launch_bounds__(256, 2)
void mega_kernel(const float* __restrict__ mf, const float* __restrict__ regtab,
                 const int* __restrict__ rid,
                 const float* __restrict__ ew1, const float* __restrict__ eb1,
                 const float* __restrict__ l1g, const float* __restrict__ l1b,
                 const float* __restrict__ ew2, const float* __restrict__ eb2,
                 const float* __restrict__ l2g, const float* __restrict__ l2b,
                 const float* __restrict__ ew3, const float* __restrict__ eb3,
                 const float* __restrict__ gw1, const float* __restrict__ gb1,
                 const float* __restrict__ gw2, const float* __restrict__ gb2,
                 const float* __restrict__ gw3, const float* __restrict__ gb3,
                 const float* __restrict__ wq,  const float* __restrict__ bq,
                 const float* __restrict__ wo,  const float* __restrict__ bo,
                 const float* __restrict__ meT, const float* __restrict__ kT,
                 const float* __restrict__ v,   const float* __restrict__ mp,
                 float* __restrict__ out_pred, float* __restrict__ out_w,
                 float* __restrict__ divp, float* __restrict__ out_div)
{
    extern __shared__ float sm[];
    float* xsA   = sm;
    float* xsB   = xsA + 1024;
    float* ctxs  = xsB + 1024;
    float* sc    = ctxs + 1024;
    float* wred  = sc + 6400;
    float* stats = wred + 64;
    __shared__ int lastFlag;

    const int t  = threadIdx.x;
    const int b0 = blockIdx.x * 4;
    const bool s2 = (t < 144);
    const bool dualWarp = (t < 160);   // warps 0-4 take dual path

    if (t < 160) {
#pragma unroll
        for (int r = 0; r < 4; r++) {
            float x = (t < 128) ? mf[(b0 + r) * 128 + t]
                                : regtab[rid[b0 + r] * 32 + (t - 128)];
            xsA[t * 4 + r] = x;
        }
    }
    __syncthreads();

    float acc[4]; ull a2[2];

    // ---- enc1: K=160, LN, GELU ----
    set_bias2(a2, eb1[t]);
    gemm_col<160>(ew1, xsA, a2, t);
    unpack4(a2, acc);
    ln_apply(acc, l1g, l1b, t, wred, stats);
#pragma unroll
    for (int r = 0; r < 4; r++) acc[r] = gelu_exact(acc[r]);
    store_x(xsB, t, acc);
    __syncthreads();

    // ---- enc2 ----
    set_bias2(a2, eb2[t]);
    gemm_col<256>(ew2, xsB, a2, t);
    unpack4(a2, acc);
    ln_apply(acc, l2g, l2b, t, wred, stats);
#pragma unroll
    for (int r = 0; r < 4; r++) acc[r] = gelu_exact(acc[r]);
    store_x(xsA, t, acc);
    __syncthreads();

    // ---- enc3 -> ctx ----
    set_bias2(a2, eb3[t]);
    gemm_col<256>(ew3, xsA, a2, t);
    unpack4(a2, acc);
    store_x(ctxs, t, acc);
    __syncthreads();

    // ---- wg1 ----
    set_bias2(a2, gb1[t]);
    gemm_col<256>(gw1, ctxs, a2, t);
    unpack4(a2, acc);
#pragma unroll
    for (int r = 0; r < 4; r++) acc[r] = gelu_exact(acc[r]);
    store_x(xsB, t, acc);
    __syncthreads();

    // ---- wg2 ----
    set_bias2(a2, gb2[t]);
    gemm_col<256>(gw2, xsB, a2, t);
    unpack4(a2, acc);
#pragma unroll
    for (int r = 0; r < 4; r++) acc[r] = gelu_exact(acc[r]);
    store_x(xsA, t, acc);
    __syncthreads();

    // ---- wg3 -> base (kept in registers) ----
    float baseA[4], baseB[4];
    if (dualWarp) {
        ull aA[2] = {0, 0}, aB[2] = {0, 0};
        gemm_col400<256>(gw3, xsA, aA, aB, t, s2);
        unpack4(aA, baseA); unpack4(aB, baseB);
        float b1v = gb3[t], b2v = s2 ? gb3[t + 256] : 0.f;
#pragma unroll
        for (int r = 0; r < 4; r++) { baseA[r] += b1v; baseB[r] += b2v; }
    } else {
        ull aA[2] = {0, 0};
        gemm_one400<256>(gw3, xsA, aA, t);
        unpack4(aA, baseA);
        float b1v = gb3[t];
#pragma unroll
        for (int r = 0; r < 4; r++) { baseA[r] += b1v; baseB[r] = 0.f; }
    }

    // ---- q = ctx@wq + bq ----
    set_bias2(a2, bq[t]);
    gemm_col<256>(wq, ctxs, a2, t);
    unpack4(a2, acc);
    store_x(xsB, t, acc);
    __syncthreads();

    // ---- scores per head -> sc[h][m][r] ----
#pragma unroll
    for (int h = 0; h < 4; h++) {
        if (dualWarp) {
            ull aA[2] = {0, 0}, aB[2] = {0, 0};
            gemm_col400<64>(kT + h * 64 * 400, xsB + h * 64 * 4, aA, aB, t, s2);
            float sA[4], sB[4];
            unpack4(aA, sA); unpack4(aB, sB);
            *(float4*)&sc[(h * 400 + t) * 4] =
                make_float4(sA[0]*0.125f, sA[1]*0.125f, sA[2]*0.125f, sA[3]*0.125f);
            if (s2)
                *(float4*)&sc[(h * 400 + t + 256) * 4] =
                    make_float4(sB[0]*0.125f, sB[1]*0.125f, sB[2]*0.125f, sB[3]*0.125f);
        } else {
            ull aA[2] = {0, 0};
            gemm_one400<64>(kT + h * 64 * 400, xsB + h * 64 * 4, aA, t);
            float sA[4]; unpack4(aA, sA);
            *(float4*)&sc[(h * 400 + t) * 4] =
                make_float4(sA[0]*0.125f, sA[1]*0.125f, sA[2]*0.125f, sA[3]*0.125f);
        }
    }
    __syncthreads();

    // ---- softmax over m for each (h, r): 16 pairs, warp each ----
    {
        int warp = t >> 5, lane = t & 31;
        for (int p = warp; p < 16; p += 8) {
            int h = p >> 2, r = p & 3;
            float* base = sc + h * 400 * 4 + r;
            float mx = -1e30f;
            for (int m = lane; m < 400; m += 32) mx = fmaxf(mx, base[m * 4]);
#pragma unroll
            for (int o = 16; o; o >>= 1) mx = fmaxf(mx, __shfl_xor_sync(0xffffffffu, mx, o));
            float s = 0.f;
            for (int m = lane; m < 400; m += 32) {
                float e = expf(base[m * 4] - mx);
                base[m * 4] = e;
                s += e;
            }
#pragma unroll
            for (int o = 16; o; o >>= 1) s += __shfl_xor_sync(0xffffffffu, s, o);
            float inv = 1.f / s;
            for (int m = lane; m < 400; m += 32) base[m * 4] *= inv;
        }
    }
    __syncthreads();

    // ---- att[r][t] = sum_m a[h(t)][r][m] * v[m][t] ----
    { ull z[2] = {0, 0};
      gemm_col<400>(v, sc + (t >> 6) * 400 * 4, z, t);
      unpack4(z, acc); }
    store_x(xsA, t, acc);
    __syncthreads();

    // ---- attended = att@wo + bo ----
    set_bias2(a2, bo[t]);
    gemm_col<256>(wo, xsA, a2, t);
    unpack4(a2, acc);
    store_x(xsB, t, acc);
    __syncthreads();

    // ---- attention_weights = attended @ me^T ----
    float awA[4], awB[4];
    if (dualWarp) {
        ull aA[2] = {0, 0}, aB[2] = {0, 0};
        gemm_col400<256>(meT, xsB, aA, aB, t, s2);
        unpack4(aA, awA); unpack4(aB, awB);
    } else {
        ull aA[2] = {0, 0};
        gemm_one400<256>(meT, xsB, aA, t);
        unpack4(aA, awA);
#pragma unroll
        for (int r = 0; r < 4; r++) awB[r] = 0.f;
    }

    // ---- combine: softmax -> clip -> renorm -> w, prediction, diversity ----
    float lA[4], lB[4], m4[4];
#pragma unroll
    for (int r = 0; r < 4; r++) {
        lA[r] = baseA[r] + 0.5f * awA[r];
        lB[r] = s2 ? (baseB[r] + 0.5f * awB[r]) : -1e30f;
        m4[r] = fmaxf(lA[r], lB[r]);
    }
    bmax4(m4, wred, stats, t);
    float eA[4], eB[4];
#pragma unroll
    for (int r = 0; r < 4; r++) {
        float mx = stats[r];
        eA[r] = expf(lA[r] - mx);
        eB[r] = s2 ? expf(lB[r] - mx) : 0.f;
        m4[r] = eA[r] + eB[r];
    }
    bsum4(m4, wred, stats, t);
    float wA[4], wB[4];
#pragma unroll
    for (int r = 0; r < 4; r++) {
        float inv = 1.f / stats[r];
        wA[r] = fmaxf(eA[r] * inv, 0.001f);
        wB[r] = s2 ? fmaxf(eB[r] * inv, 0.001f) : 0.f;
        m4[r] = wA[r] + wB[r];
    }
    bsum4(m4, wred, stats, t);

    float p0[4], p1[4], p2[4], sx[4], sy[4], sz[4], tt[4];
#pragma unroll
    for (int r = 0; r < 4; r++) {
        float inv2 = 1.f / stats[r];
        wA[r] *= inv2;
        out_w[(size_t)(b0 + r) * 400 + t] = wA[r];
        const float* q1 = mp + ((size_t)(b0 + r) * 400 + t) * 3;
        float x0 = q1[0], x1 = q1[1], x2 = q1[2];
        float n2 = x0 * x0 + x1 * x1 + x2 * x2;
        float invn = 1.f / fmaxf(sqrtf(n2), 1e-12f);
        p0[r] = wA[r] * x0; p1[r] = wA[r] * x1; p2[r] = wA[r] * x2;
        sx[r] = x0 * invn;  sy[r] = x1 * invn;  sz[r] = x2 * invn;
        tt[r] = n2 * invn * invn;
        if (s2) {
            wB[r] *= inv2;
            out_w[(size_t)(b0 + r) * 400 + t + 256] = wB[r];
            const float* q2 = mp + ((size_t)(b0 + r) * 400 + t + 256) * 3;
            float y0 = q2[0], y1 = q2[1], y2 = q2[2];
            float nn = y0 * y0 + y1 * y1 + y2 * y2;
            float iv = 1.f / fmaxf(sqrtf(nn), 1e-12f);
            p0[r] += wB[r] * y0; p1[r] += wB[r] * y1; p2[r] += wB[r] * y2;
            sx[r] += y0 * iv;    sy[r] += y1 * iv;    sz[r] += y2 * iv;
            tt[r] += nn * iv * iv;
        }
    }
    bsum4(p0, wred, stats, t); float P0 = stats[t & 3];
    bsum4(p1, wred, stats, t); float P1 = stats[t & 3];
    bsum4(p2, wred, stats, t); float P2 = stats[t & 3];
    bsum4(sx, wred, stats, t); float SX = stats[t & 3];
    bsum4(sy, wred, stats, t); float SY = stats[t & 3];
    bsum4(sz, wred, stats, t); float SZ = stats[t & 3];
    bsum4(tt, wred, stats, t); float TT = stats[t & 3];
    if (t < 4) {
        out_pred[(b0 + t) * 3 + 0] = P0;
        out_pred[(b0 + t) * 3 + 1] = P1;
        out_pred[(b0 + t) * 3 + 2] = P2;
        divp[b0 + t] = SX * SX + SY * SY + SZ * SZ - TT;
    }

    // ---- last-block deterministic final reduction ----
    __syncthreads();
    if (t == 0) {
        __threadfence();
        int c = atomicAdd(&g_cnt, 1);
        lastFlag = (c == (int)gridDim.x - 1);
    }
    __syncthreads();
    if (lastFlag) {
        float s = 0.f;
        for (int i = t; i < 1024; i += 256) s += divp[i];
        int lane = t & 31, warp = t >> 5;
#pragma unroll
        for (int o = 16; o; o >>= 1) s += __shfl_xor_sync(0xffffffffu, s, o);
        if (lane == 0) wred[warp] = s;
        __syncthreads();
        if (t == 0) {
            float tot = 0.f;
#pragma unroll
            for (int w = 0; w < 8; w++) tot += wred[w];
            out_div[0] = tot / (1024.0f * 400.0f * 399.0f) * 0.1f;
            g_cnt = 0;
        }
    }
}

// =================================================================
extern "C" void kernel_launch(void* const* d_in, const int* in_sizes, int n_in,
                              void* d_out, int out_size)
{
    const float* mf     = (const float*)d_in[0];
    const float* mp     = (const float*)d_in[1];
    const float* regtab = (const float*)d_in[2];
    const float* enc_w1 = (const float*)d_in[3];
    const float* enc_b1 = (const float*)d_in[4];
    const float* ln1g   = (const float*)d_in[5];
    const float* ln1b   = (const float*)d_in[6];
    const float* enc_w2 = (const float*)d_in[7];
    const float* enc_b2 = (const float*)d_in[8];
    const float* ln2g   = (const float*)d_in[9];
    const float* ln2b   = (const float*)d_in[10];
    const float* enc_w3 = (const float*)d_in[11];
    const float* enc_b3 = (const float*)d_in[12];
    const float* wg_w1  = (const float*)d_in[13];
    const float* wg_b1  = (const float*)d_in[14];
    const float* wg_w2  = (const float*)d_in[15];
    const float* wg_b2  = (const float*)d_in[16];
    const float* wg_w3  = (const float*)d_in[17];
    const float* wg_b3  = (const float*)d_in[18];
    const float* memb   = (const float*)d_in[19];
    const float* proj_w = (const float*)d_in[20];
    const float* proj_b = (const float*)d_in[21];
    const float* wq     = (const float*)d_in[22];
    const float* bq     = (const float*)d_in[23];
    const float* wk     = (const float*)d_in[24];
    const float* bk     = (const float*)d_in[25];
    const float* wv     = (const float*)d_in[26];
    const float* bv     = (const float*)d_in[27];
    const float* wo     = (const float*)d_in[28];
    const float* bo     = (const float*)d_in[29];
    const int*   rid    = (const int*)d_in[30];
    float* out = (float*)d_out;

    float *meT, *kT, *v, *divp;
    cudaGetSymbolAddress((void**)&meT,  g_meT);
    cudaGetSymbolAddress((void**)&kT,   g_kT);
    cudaGetSymbolAddress((void**)&v,    g_v);
    cudaGetSymbolAddress((void**)&divp, g_div);

    const int smem_bytes = SM_FLOATS * (int)sizeof(float);
    cudaFuncSetAttribute(mega_kernel, cudaFuncAttributeMaxDynamicSharedMemorySize,
                         smem_bytes);

    prep_kernel<<<dim3(100, 2), 256>>>(memb, proj_w, proj_b, wk, bk, wv, bv,
                                       meT, kT, v);

    mega_kernel<<<256, 256, smem_bytes>>>(
        mf, regtab, rid,
        enc_w1, enc_b1, ln1g, ln1b,
        enc_w2, enc_b2, ln2g, ln2b,
        enc_w3, enc_b3,
        wg_w1, wg_b1, wg_w2, wg_b2, wg_w3, wg_b3,
        wq, bq, wo, bo,
        meT, kT, v, mp,
        out, out + 3072, divp, out + 412672);
}